// round 16
// baseline (speedup 1.0000x reference)
#include <cuda_runtime.h>

#define TPB 256
#define COLS_PER_BLOCK 512   // 2 float4 columns per thread, block-strided

// Single fused kernel. Thread 0 builds the 3x4 SE3 matrix (exact fp32
// reference math) into shared memory; all threads broadcast-read it, then
// stream 2 block-strided float4 columns. All blocks except the last take an
// unconditional path so ptxas front-batches all 8 LDG.128 (MLP=8).
__global__ __launch_bounds__(TPB)
void se3_fused_mlp8(const float4* __restrict__ x, float4* __restrict__ y,
                    const float* __restrict__ w, const float* __restrict__ v,
                    const float* __restrict__ theta_p, int n4) {
    __shared__ float sM[12];

    if (threadIdx.x == 0) {
        const float wx = w[0], wy = w[1], wz = w[2];
        const float theta = theta_p[0];
        const float s = sinf(theta);
        const float c = cosf(theta);
        const float omc = 1.0f - c;     // 1 - cos(theta)
        const float tms = theta - s;    // theta - sin(theta)

        // K = skew(w); KK = K @ K
        const float K[9] = { 0.0f, -wz,   wy,
                             wz,    0.0f, -wx,
                            -wy,    wx,   0.0f };
        float KK[9];
        #pragma unroll
        for (int r = 0; r < 3; r++)
            #pragma unroll
            for (int col = 0; col < 3; col++) {
                float acc = 0.0f;
                #pragma unroll
                for (int k = 0; k < 3; k++) acc += K[r * 3 + k] * K[k * 3 + col];
                KK[r * 3 + col] = acc;
            }

        const float vx = v[0], vy = v[1], vz = v[2];
        #pragma unroll
        for (int r = 0; r < 3; r++) {
            float Vr[3];
            #pragma unroll
            for (int col = 0; col < 3; col++) {
                const float I = (r == col) ? 1.0f : 0.0f;
                sM[r * 4 + col] = I + s * K[r * 3 + col] + omc * KK[r * 3 + col];
                Vr[col]         = I * theta + omc * K[r * 3 + col] + tms * KK[r * 3 + col];
            }
            sM[r * 4 + 3] = Vr[0] * vx + Vr[1] * vy + Vr[2] * vz;
        }
    }
    __syncthreads();

    const float m00 = sM[0], m01 = sM[1], m02 = sM[2],  m03 = sM[3];
    const float m10 = sM[4], m11 = sM[5], m12 = sM[6],  m13 = sM[7];
    const float m20 = sM[8], m21 = sM[9], m22 = sM[10], m23 = sM[11];

    const size_t stride = (size_t)n4;
    const size_t i0 = (size_t)blockIdx.x * COLS_PER_BLOCK + threadIdx.x;
    const size_t i1 = i0 + TPB;

#define SE3_COL(xx0, xx1, xx2, xx3, idx)                                      \
    do {                                                                      \
        float4 y0, y1, y2;                                                    \
        y0.x = m00*(xx0).x + m01*(xx1).x + m02*(xx2).x + m03*(xx3).x;         \
        y0.y = m00*(xx0).y + m01*(xx1).y + m02*(xx2).y + m03*(xx3).y;         \
        y0.z = m00*(xx0).z + m01*(xx1).z + m02*(xx2).z + m03*(xx3).z;         \
        y0.w = m00*(xx0).w + m01*(xx1).w + m02*(xx2).w + m03*(xx3).w;         \
        y1.x = m10*(xx0).x + m11*(xx1).x + m12*(xx2).x + m13*(xx3).x;         \
        y1.y = m10*(xx0).y + m11*(xx1).y + m12*(xx2).y + m13*(xx3).y;         \
        y1.z = m10*(xx0).z + m11*(xx1).z + m12*(xx2).z + m13*(xx3).z;         \
        y1.w = m10*(xx0).w + m11*(xx1).w + m12*(xx2).w + m13*(xx3).w;         \
        y2.x = m20*(xx0).x + m21*(xx1).x + m22*(xx2).x + m23*(xx3).x;         \
        y2.y = m20*(xx0).y + m21*(xx1).y + m22*(xx2).y + m23*(xx3).y;         \
        y2.z = m20*(xx0).z + m21*(xx1).z + m22*(xx2).z + m23*(xx3).z;         \
        y2.w = m20*(xx0).w + m21*(xx1).w + m22*(xx2).w + m23*(xx3).w;         \
        __stcs(y + 0 * stride + (idx), y0);                                   \
        __stcs(y + 1 * stride + (idx), y1);                                   \
        __stcs(y + 2 * stride + (idx), y2);                                   \
        __stcs(y + 3 * stride + (idx), (xx3));                                \
    } while (0)

    if (blockIdx.x != gridDim.x - 1) {
        // Full tile: 8 unconditional front-batched loads (MLP=8), then compute+store.
        const float4 a0 = __ldcs(x + 0 * stride + i0);
        const float4 a1 = __ldcs(x + 1 * stride + i0);
        const float4 a2 = __ldcs(x + 2 * stride + i0);
        const float4 a3 = __ldcs(x + 3 * stride + i0);
        const float4 b0 = __ldcs(x + 0 * stride + i1);
        const float4 b1 = __ldcs(x + 1 * stride + i1);
        const float4 b2 = __ldcs(x + 2 * stride + i1);
        const float4 b3 = __ldcs(x + 3 * stride + i1);
        SE3_COL(a0, a1, a2, a3, i0);
        SE3_COL(b0, b1, b2, b3, i1);
    } else {
        // Last (possibly partial) tile: guarded per column.
        if (i0 < stride) {
            const float4 a0 = __ldcs(x + 0 * stride + i0);
            const float4 a1 = __ldcs(x + 1 * stride + i0);
            const float4 a2 = __ldcs(x + 2 * stride + i0);
            const float4 a3 = __ldcs(x + 3 * stride + i0);
            SE3_COL(a0, a1, a2, a3, i0);
        }
        if (i1 < stride) {
            const float4 b0 = __ldcs(x + 0 * stride + i1);
            const float4 b1 = __ldcs(x + 1 * stride + i1);
            const float4 b2 = __ldcs(x + 2 * stride + i1);
            const float4 b3 = __ldcs(x + 3 * stride + i1);
            SE3_COL(b0, b1, b2, b3, i1);
        }
    }
#undef SE3_COL
}

// Scalar tail for N not divisible by 4 (defensive; N=16M is divisible).
__global__ void se3_tail(const float* __restrict__ x, float* __restrict__ y,
                         const float* __restrict__ w, const float* __restrict__ v,
                         const float* __restrict__ theta_p, int N, int start) {
    const int i = start + blockIdx.x * blockDim.x + threadIdx.x;
    if (i >= N) return;

    const float wx = w[0], wy = w[1], wz = w[2];
    const float theta = theta_p[0];
    const float s = sinf(theta), c = cosf(theta);
    const float omc = 1.0f - c, tms = theta - s;
    const float K[9] = { 0.0f, -wz, wy,  wz, 0.0f, -wx,  -wy, wx, 0.0f };
    float KK[9];
    for (int r = 0; r < 3; r++)
        for (int col = 0; col < 3; col++) {
            float acc = 0.0f;
            for (int k = 0; k < 3; k++) acc += K[r * 3 + k] * K[k * 3 + col];
            KK[r * 3 + col] = acc;
        }
    float M[12];
    for (int r = 0; r < 3; r++) {
        float Vr[3];
        for (int col = 0; col < 3; col++) {
            const float I = (r == col) ? 1.0f : 0.0f;
            M[r * 4 + col] = I + s * K[r * 3 + col] + omc * KK[r * 3 + col];
            Vr[col]        = I * theta + omc * K[r * 3 + col] + tms * KK[r * 3 + col];
        }
        M[r * 4 + 3] = Vr[0] * v[0] + Vr[1] * v[1] + Vr[2] * v[2];
    }

    const float a  = x[0 * (size_t)N + i];
    const float b  = x[1 * (size_t)N + i];
    const float cc = x[2 * (size_t)N + i];
    const float d  = x[3 * (size_t)N + i];
    y[0 * (size_t)N + i] = M[0] * a + M[1] * b + M[2]  * cc + M[3]  * d;
    y[1 * (size_t)N + i] = M[4] * a + M[5] * b + M[6]  * cc + M[7]  * d;
    y[2 * (size_t)N + i] = M[8] * a + M[9] * b + M[10] * cc + M[11] * d;
    y[3 * (size_t)N + i] = d;
}

extern "C" void kernel_launch(void* const* d_in, const int* in_sizes, int n_in,
                              void* d_out, int out_size) {
    const float* x     = (const float*)d_in[0];   // [4, N]
    const float* w     = (const float*)d_in[1];   // [3]
    const float* v     = (const float*)d_in[2];   // [3]
    const float* theta = (const float*)d_in[3];   // scalar

    const int N   = in_sizes[0] / 4;
    const int n4  = N / 4;
    const int rem = N - n4 * 4;

    if (n4 > 0) {
        const int blocks = (n4 + COLS_PER_BLOCK - 1) / COLS_PER_BLOCK;
        se3_fused_mlp8<<<blocks, TPB>>>((const float4*)x, (float4*)d_out,
                                        w, v, theta, n4);
    }
    if (rem > 0) {
        se3_tail<<<1, 128>>>(x, (float*)d_out, w, v, theta, N, n4 * 4);
    }
}